// round 6
// baseline (speedup 1.0000x reference)
#include <cuda_runtime.h>
#include <cuda_bf16.h>

// Problem constants (from reference setup_inputs)
#define Bc 2
#define Tc 2048
#define Dc 1024
#define Nc 16
#define Lc 16
#define Cc 128                 // Tc / Lc
#define S_TOT (Bc*Dc*Nc)       // 32768 states
#define PQ_TOT (Cc*S_TOT)      // 4,194,304

// Scratch (static device arrays — no allocation allowed)
__device__ float g_P[PQ_TOT];
__device__ float g_Q[PQ_TOT];
__device__ float g_H0[PQ_TOT];

// ---------------------------------------------------------------------------
// Clip identity: A < 0  =>  max(dl*A, -10) = A * min(dl, -10/A).
// t-accumulation becomes W[n] = sum_t min(dl_t, thr_n)  (1 MNMX + 1 FADD),
// with the multiply by A hoisted out: P = exp(A*W).
// ---------------------------------------------------------------------------

// ---------------------------------------------------------------------------
// Kernel A: per-chunk carry coefficients. Thread = (b,k,d), ALL 16 n in regs
// (R4 mapping: consecutive lanes = consecutive d -> 128B-coalesced delta).
//   P_k[n] = exp( A_n * W[n] )
//   Q_k[n] = frac0[n] * b0[n] * u0 * eA0[n]   (fw[0] = eA[0] since L>1)
// ---------------------------------------------------------------------------
__global__ __launch_bounds__(256) void pq_kernel(
    const float* __restrict__ u,
    const float* __restrict__ delta,
    const float* __restrict__ bmat,
    const float* __restrict__ Alog)
{
    int bx = blockIdx.x;
    int dblk = bx & 3;           // 4 d-blocks of 256
    int k    = (bx >> 2) & 127;
    int b    = bx >> 9;
    int d    = dblk * 256 + threadIdx.x;

    float A[Nc], thr[Nc];
#pragma unroll
    for (int n = 0; n < Nc; ++n) {
        A[n]   = -__expf(Alog[n]);
        thr[n] = -10.0f / A[n];
    }

    int base_td = (b * Tc + k * Lc) * Dc + d;

    float W[Nc];
#pragma unroll
    for (int n = 0; n < Nc; ++n) W[n] = 0.0f;

    float dl0 = 0.0f;
#pragma unroll
    for (int t = 0; t < Lc; ++t) {
        float dl = delta[base_td + t * Dc];
        if (t == 0) dl0 = dl;
#pragma unroll
        for (int n = 0; n < Nc; ++n)
            W[n] += fminf(dl, thr[n]);
    }

    float u0 = u[base_td];
    const float4* b0p = reinterpret_cast<const float4*>(bmat + (size_t)base_td * Nc);

    int sbase = k * S_TOT + (b * Dc + d) * Nc;
    float4* Pp = reinterpret_cast<float4*>(g_P + sbase);
    float4* Qp = reinterpret_cast<float4*>(g_Q + sbase);

#pragma unroll
    for (int q = 0; q < 4; ++q) {
        float4 b0 = b0p[q];
        float bv[4] = {b0.x, b0.y, b0.z, b0.w};
        float Pv[4], Qv[4];
#pragma unroll
        for (int i = 0; i < 4; ++i) {
            int n = q * 4 + i;
            float invA = 1.0f / (A[n] + 1e-12f);
            Pv[i] = __expf(A[n] * W[n]);
            float da0 = A[n] * fminf(dl0, thr[n]);
            float eA0 = __expf(da0);
            float frac0 = (fabsf(da0) < 1e-4f) ? (da0 * invA) : (eA0 - 1.0f) * invA;
            Qv[i] = frac0 * bv[i] * u0 * eA0;
        }
        Pp[q] = make_float4(Pv[0], Pv[1], Pv[2], Pv[3]);
        Qp[q] = make_float4(Qv[0], Qv[1], Qv[2], Qv[3]);
    }
}

// ---------------------------------------------------------------------------
// Kernel B: serial scan over the 128 chunks per state.
//   h0[k] = h (state entering chunk k);  h <- h*P[k] + Q[k]
// ---------------------------------------------------------------------------
__global__ __launch_bounds__(256) void scan_kernel()
{
    int s = blockIdx.x * blockDim.x + threadIdx.x;
    float h = 0.0f;
    for (int kk = 0; kk < Cc; kk += 8) {
        float Pv[8], Qv[8];
#pragma unroll
        for (int j = 0; j < 8; ++j) {
            Pv[j] = g_P[(kk + j) * S_TOT + s];
            Qv[j] = g_Q[(kk + j) * S_TOT + s];
        }
#pragma unroll
        for (int j = 0; j < 8; ++j) {
            g_H0[(kk + j) * S_TOT + s] = h;
            h = fmaf(h, Pv[j], Qv[j]);
        }
    }
}

// ---------------------------------------------------------------------------
// Kernel C: main pass. Thread = (b,k,d, n-quad): 4 consecutive n per thread.
//   Phase 1 stores dl[16] in REGISTERS (16 regs, vs R4's 64-reg dA table)
//   and accumulates Wtot. Phase 2 walks ps (ascending j) and Wr (descending
//   t_idx = 15-j) with the Wr chain entirely in registers:
//     cumA[t_idx] = exp(A*Wr);  Wr -= min(dl[t_idx], thr)     (4-cyc chain)
//   y[t_idx] = sum_n (h0*cumA[t_idx] + PS[j]) * c[t_idx].
//   2x shfl_xor reduces the n-quad lanes; y staged in smem, coalesced write.
// ---------------------------------------------------------------------------
__global__ __launch_bounds__(256, 3) void main_kernel(
    const float* __restrict__ u,
    const float* __restrict__ delta,
    const float* __restrict__ bmat,
    const float* __restrict__ cmat,
    const float* __restrict__ Alog,
    float* __restrict__ y)
{
    int bx = blockIdx.x;
    int dblk = bx & 15;          // 16 d-blocks of 64
    int k    = (bx >> 4) & 127;  // chunk
    int b    = bx >> 11;         // batch

    int tid  = threadIdx.x;
    int ng   = tid & 3;          // n-quad: n = 4*ng .. 4*ng+3
    int dloc = tid >> 2;         // 0..63
    int d    = dblk * 64 + dloc;

    float A[4], invA[4], thr[4];
#pragma unroll
    for (int i = 0; i < 4; ++i) {
        A[i]    = -__expf(Alog[4 * ng + i]);
        invA[i] = 1.0f / (A[i] + 1e-12f);
        thr[i]  = -10.0f / A[i];
    }

    int base_td = (b * Tc + k * Lc) * Dc + d;

    // Phase 1: dl table (16 regs) + Wtot
    float dl[Lc];
    float Wr[4] = {0.0f, 0.0f, 0.0f, 0.0f};
#pragma unroll
    for (int t = 0; t < Lc; ++t) {
        dl[t] = delta[base_td + t * Dc];
#pragma unroll
        for (int i = 0; i < 4; ++i)
            Wr[i] += fminf(dl[t], thr[i]);
    }

    float4 h04 = *reinterpret_cast<const float4*>(
        g_H0 + k * S_TOT + (b * Dc + d) * Nc + 4 * ng);
    float h0[4] = {h04.x, h04.y, h04.z, h04.w};

    __shared__ float s_y[Lc * 64];

    float ps[4] = {0.0f, 0.0f, 0.0f, 0.0f};

#pragma unroll
    for (int j = 0; j < Lc; ++j) {
        int t_idx = Lc - 1 - j;
        float uu = u[base_td + j * Dc];
        float4 b4 = *reinterpret_cast<const float4*>(
            bmat + (size_t)(base_td + j * Dc) * Nc + 4 * ng);
        float4 c4 = *reinterpret_cast<const float4*>(
            cmat + (size_t)(base_td + t_idx * Dc) * Nc + 4 * ng);
        float bv[4] = {b4.x, b4.y, b4.z, b4.w};
        float cv[4] = {c4.x, c4.y, c4.z, c4.w};

        float contrib = 0.0f;
#pragma unroll
        for (int i = 0; i < 4; ++i) {
            float cumA = __expf(A[i] * Wr[i]);      // cumprod(eA)[t_idx]
            Wr[i] -= fminf(dl[t_idx], thr[i]);      // register-only chain

            float da = A[i] * fminf(dl[j], thr[i]);
            float eA = __expf(da);
            float frac = (fabsf(da) < 1e-4f) ? (da * invA[i])
                                             : (eA - 1.0f) * invA[i];
            float bu = frac * bv[i] * uu;
            float fw = (j == Lc - 1) ? 1.0f : eA;   // folds at compile time
            ps[i] += bu * fw;                       // ps = PS[j]
            contrib = fmaf(fmaf(h0[i], cumA, ps[i]), cv[i], contrib);
        }
        // reduce over the 4 n-quad lanes (bits 0..1 of lane id)
        contrib += __shfl_xor_sync(0xffffffffu, contrib, 1, 32);
        contrib += __shfl_xor_sync(0xffffffffu, contrib, 2, 32);
        if (ng == 0) s_y[t_idx * 64 + dloc] = contrib;
    }
    __syncthreads();

    // coalesced y writes: 4 rows of 256
#pragma unroll
    for (int r = 0; r < 4; ++r) {
        int idx = tid + r * 256;
        int tt = idx >> 6;
        int dw = idx & 63;
        y[(b * Tc + k * Lc + tt) * Dc + dblk * 64 + dw] = s_y[idx];
    }
}

// ---------------------------------------------------------------------------
extern "C" void kernel_launch(void* const* d_in, const int* in_sizes, int n_in,
                              void* d_out, int out_size)
{
    const float* u     = (const float*)d_in[0];
    const float* delta = (const float*)d_in[1];
    const float* bmat  = (const float*)d_in[2];
    const float* cmat  = (const float*)d_in[3];
    const float* Alog  = (const float*)d_in[4];
    float* y = (float*)d_out;

    pq_kernel<<<Bc * Cc * 4, 256>>>(u, delta, bmat, Alog);
    scan_kernel<<<S_TOT / 256, 256>>>();
    main_kernel<<<Bc * Cc * 16, 256>>>(u, delta, bmat, cmat, Alog, y);
}

// round 7
// speedup vs baseline: 1.0964x; 1.0964x over previous
#include <cuda_runtime.h>
#include <cuda_bf16.h>

// Problem constants (from reference setup_inputs)
#define Bc 2
#define Tc 2048
#define Dc 1024
#define Nc 16
#define Lc 16
#define Cc 128                 // Tc / Lc
#define S_TOT (Bc*Dc*Nc)       // 32768 states
#define PQ_TOT (Cc*S_TOT)      // 4,194,304

// Scratch (static device arrays — no allocation allowed)
__device__ float g_P[PQ_TOT];
__device__ float g_Q[PQ_TOT];
__device__ float g_H0[PQ_TOT];

// ---------------------------------------------------------------------------
// Kernel A (R4-proven version): thread = (b,k,d), ALL 16 n in regs.
//   P_k[n] = exp( sum_t max(dl_t*A_n, -10) )
//   Q_k[n] = frac0[n] * b0[n] * u0 * eA0[n]   (fw[0] = eA[0] since L>1)
// ---------------------------------------------------------------------------
__global__ __launch_bounds__(256) void pq_kernel(
    const float* __restrict__ u,
    const float* __restrict__ delta,
    const float* __restrict__ bmat,
    const float* __restrict__ Alog)
{
    int bx = blockIdx.x;
    int dblk = bx & 3;           // 4 d-blocks of 256
    int k    = (bx >> 2) & 127;
    int b    = bx >> 9;
    int d    = dblk * 256 + threadIdx.x;

    float A[Nc];
#pragma unroll
    for (int n = 0; n < Nc; ++n) A[n] = -__expf(Alog[n]);

    int base_td = (b * Tc + k * Lc) * Dc + d;

    float S[Nc];
#pragma unroll
    for (int n = 0; n < Nc; ++n) S[n] = 0.0f;

    float dl0 = 0.0f;
#pragma unroll
    for (int t = 0; t < Lc; ++t) {
        float dl = delta[base_td + t * Dc];
        if (t == 0) dl0 = dl;
#pragma unroll
        for (int n = 0; n < Nc; ++n)
            S[n] += fmaxf(dl * A[n], -10.0f);
    }

    float u0 = u[base_td];
    const float4* b0p = reinterpret_cast<const float4*>(bmat + (size_t)base_td * Nc);

    int sbase = k * S_TOT + (b * Dc + d) * Nc;
    float4* Pp = reinterpret_cast<float4*>(g_P + sbase);
    float4* Qp = reinterpret_cast<float4*>(g_Q + sbase);

#pragma unroll
    for (int q = 0; q < 4; ++q) {
        float4 b0 = b0p[q];
        float bv[4] = {b0.x, b0.y, b0.z, b0.w};
        float Pv[4], Qv[4];
#pragma unroll
        for (int i = 0; i < 4; ++i) {
            int n = q * 4 + i;
            float invA = 1.0f / (A[n] + 1e-12f);
            Pv[i] = __expf(S[n]);
            float da0 = fmaxf(dl0 * A[n], -10.0f);
            float eA0 = __expf(da0);
            float frac0 = (fabsf(da0) < 1e-4f) ? (da0 * invA) : (eA0 - 1.0f) * invA;
            Qv[i] = frac0 * bv[i] * u0 * eA0;
        }
        Pp[q] = make_float4(Pv[0], Pv[1], Pv[2], Pv[3]);
        Qp[q] = make_float4(Qv[0], Qv[1], Qv[2], Qv[3]);
    }
}

// ---------------------------------------------------------------------------
// Kernel B: serial scan over the 128 chunks per state.
// ---------------------------------------------------------------------------
__global__ __launch_bounds__(256) void scan_kernel()
{
    int s = blockIdx.x * blockDim.x + threadIdx.x;
    float h = 0.0f;
    for (int kk = 0; kk < Cc; kk += 8) {
        float Pv[8], Qv[8];
#pragma unroll
        for (int j = 0; j < 8; ++j) {
            Pv[j] = g_P[(kk + j) * S_TOT + s];
            Qv[j] = g_Q[(kk + j) * S_TOT + s];
        }
#pragma unroll
        for (int j = 0; j < 8; ++j) {
            g_H0[(kk + j) * S_TOT + s] = h;
            h = fmaf(h, Pv[j], Qv[j]);
        }
    }
}

// ---------------------------------------------------------------------------
// Kernel C: main pass, single ASCENDING loop, no register tables.
//   y[t] = sum_n h0*cumA[t]*c[t]  +  sum_n PS[15-t]*c[t]
// At iteration t we have cumA[t] (running product, 1 exp per (i,t) total)
// and PS[t] (running prefix). Piece A -> s_y[t]; piece B = sum_n PS[t]*c[15-t]
// -> s_y[15-t] (c reloaded at mirror index: same 64KB block tile, L2-hot).
// Each s_y slot is touched twice by the SAME thread (iters t and 15-t):
// first 8 iterations store, last 8 accumulate.
// Persistent state: A,invA,h0,cum,ps = 20 regs -> 4 blocks/SM, 2x MLP vs R4.
// ---------------------------------------------------------------------------
__global__ __launch_bounds__(256, 4) void main_kernel(
    const float* __restrict__ u,
    const float* __restrict__ delta,
    const float* __restrict__ bmat,
    const float* __restrict__ cmat,
    const float* __restrict__ Alog,
    float* __restrict__ y)
{
    int bx = blockIdx.x;
    int dblk = bx & 15;          // 16 d-blocks of 64
    int k    = (bx >> 4) & 127;  // chunk
    int b    = bx >> 11;         // batch

    int tid  = threadIdx.x;
    int ng   = tid & 3;          // n-quad: n = 4*ng .. 4*ng+3
    int dloc = tid >> 2;         // 0..63
    int d    = dblk * 64 + dloc;

    float A[4], invA[4];
#pragma unroll
    for (int i = 0; i < 4; ++i) {
        A[i]    = -__expf(Alog[4 * ng + i]);
        invA[i] = 1.0f / (A[i] + 1e-12f);
    }

    int base_td = (b * Tc + k * Lc) * Dc + d;

    float4 h04 = *reinterpret_cast<const float4*>(
        g_H0 + k * S_TOT + (b * Dc + d) * Nc + 4 * ng);
    float h0[4] = {h04.x, h04.y, h04.z, h04.w};

    __shared__ float s_y[Lc * 64];

    float cum[4] = {1.0f, 1.0f, 1.0f, 1.0f};
    float ps[4]  = {0.0f, 0.0f, 0.0f, 0.0f};

#pragma unroll
    for (int t = 0; t < Lc; ++t) {
        int tr = Lc - 1 - t;
        float dl = delta[base_td + t * Dc];
        float uu = u[base_td + t * Dc];
        float4 b4 = *reinterpret_cast<const float4*>(
            bmat + (size_t)(base_td + t * Dc) * Nc + 4 * ng);
        float4 c4 = *reinterpret_cast<const float4*>(
            cmat + (size_t)(base_td + t * Dc) * Nc + 4 * ng);
        float4 cr4 = *reinterpret_cast<const float4*>(
            cmat + (size_t)(base_td + tr * Dc) * Nc + 4 * ng);
        float bv[4]  = {b4.x, b4.y, b4.z, b4.w};
        float cv[4]  = {c4.x, c4.y, c4.z, c4.w};
        float crv[4] = {cr4.x, cr4.y, cr4.z, cr4.w};

        float cA = 0.0f, cB = 0.0f;
#pragma unroll
        for (int i = 0; i < 4; ++i) {
            float da = fmaxf(dl * A[i], -10.0f);
            float eA = __expf(da);
            cum[i] *= eA;                       // cumA[t] (inclusive)
            float frac = (fabsf(da) < 1e-4f) ? (da * invA[i])
                                             : (eA - 1.0f) * invA[i];
            float bu = frac * bv[i] * uu;
            float fw = (t == Lc - 1) ? 1.0f : eA;   // folds at compile time
            ps[i] += bu * fw;                   // PS[t] (inclusive)
            cA = fmaf(h0[i] * cum[i], cv[i], cA);
            cB = fmaf(ps[i], crv[i], cB);
        }
        // reduce over the 4 n-quad lanes (bits 0..1 of lane id)
        cA += __shfl_xor_sync(0xffffffffu, cA, 1, 32);
        cA += __shfl_xor_sync(0xffffffffu, cA, 2, 32);
        cB += __shfl_xor_sync(0xffffffffu, cB, 1, 32);
        cB += __shfl_xor_sync(0xffffffffu, cB, 2, 32);
        if (ng == 0) {
            if (t < Lc / 2) {                   // first touch: store
                s_y[t  * 64 + dloc] = cA;
                s_y[tr * 64 + dloc] = cB;
            } else {                            // second touch: accumulate
                s_y[t  * 64 + dloc] += cA;
                s_y[tr * 64 + dloc] += cB;
            }
        }
    }
    __syncthreads();

    // coalesced y writes: 4 rows of 256
#pragma unroll
    for (int r = 0; r < 4; ++r) {
        int idx = tid + r * 256;
        int tt = idx >> 6;
        int dw = idx & 63;
        y[(b * Tc + k * Lc + tt) * Dc + dblk * 64 + dw] = s_y[idx];
    }
}

// ---------------------------------------------------------------------------
extern "C" void kernel_launch(void* const* d_in, const int* in_sizes, int n_in,
                              void* d_out, int out_size)
{
    const float* u     = (const float*)d_in[0];
    const float* delta = (const float*)d_in[1];
    const float* bmat  = (const float*)d_in[2];
    const float* cmat  = (const float*)d_in[3];
    const float* Alog  = (const float*)d_in[4];
    float* y = (float*)d_out;

    pq_kernel<<<Bc * Cc * 4, 256>>>(u, delta, bmat, Alog);
    scan_kernel<<<S_TOT / 256, 256>>>();
    main_kernel<<<Bc * Cc * 16, 256>>>(u, delta, bmat, cmat, Alog, y);
}

// round 8
// speedup vs baseline: 1.3202x; 1.2042x over previous
#include <cuda_runtime.h>
#include <cuda_bf16.h>

// Problem constants (from reference setup_inputs)
#define Bc 2
#define Tc 2048
#define Dc 1024
#define Nc 16
#define Lc 16
#define Cc 128                 // Tc / Lc
#define S_TOT (Bc*Dc*Nc)       // 32768 states
#define PQ_TOT (Cc*S_TOT)      // 4,194,304

// Scratch (static device arrays — no allocation allowed)
__device__ float g_P[PQ_TOT];
__device__ float g_Q[PQ_TOT];
__device__ float g_H0[PQ_TOT];

// ---------------------------------------------------------------------------
// Kernel A (R4-proven, 18.8us): thread = (b,k,d), ALL 16 n in regs.
//   P_k[n] = exp( sum_t max(dl_t*A_n, -10) )
//   Q_k[n] = frac0[n] * b0[n] * u0 * eA0[n]   (fw[0] = eA[0] since L>1)
// ---------------------------------------------------------------------------
__global__ __launch_bounds__(256) void pq_kernel(
    const float* __restrict__ u,
    const float* __restrict__ delta,
    const float* __restrict__ bmat,
    const float* __restrict__ Alog)
{
    int bx = blockIdx.x;
    int dblk = bx & 3;           // 4 d-blocks of 256
    int k    = (bx >> 2) & 127;
    int b    = bx >> 9;
    int d    = dblk * 256 + threadIdx.x;

    float A[Nc];
#pragma unroll
    for (int n = 0; n < Nc; ++n) A[n] = -__expf(Alog[n]);

    int base_td = (b * Tc + k * Lc) * Dc + d;

    float S[Nc];
#pragma unroll
    for (int n = 0; n < Nc; ++n) S[n] = 0.0f;

    float dl0 = 0.0f;
#pragma unroll
    for (int t = 0; t < Lc; ++t) {
        float dl = delta[base_td + t * Dc];
        if (t == 0) dl0 = dl;
#pragma unroll
        for (int n = 0; n < Nc; ++n)
            S[n] += fmaxf(dl * A[n], -10.0f);
    }

    float u0 = u[base_td];
    const float4* b0p = reinterpret_cast<const float4*>(bmat + (size_t)base_td * Nc);

    int sbase = k * S_TOT + (b * Dc + d) * Nc;
    float4* Pp = reinterpret_cast<float4*>(g_P + sbase);
    float4* Qp = reinterpret_cast<float4*>(g_Q + sbase);

#pragma unroll
    for (int q = 0; q < 4; ++q) {
        float4 b0 = b0p[q];
        float bv[4] = {b0.x, b0.y, b0.z, b0.w};
        float Pv[4], Qv[4];
#pragma unroll
        for (int i = 0; i < 4; ++i) {
            int n = q * 4 + i;
            float invA = 1.0f / (A[n] + 1e-12f);
            Pv[i] = __expf(S[n]);
            float da0 = fmaxf(dl0 * A[n], -10.0f);
            float eA0 = __expf(da0);
            float frac0 = (fabsf(da0) < 1e-4f) ? (da0 * invA) : (eA0 - 1.0f) * invA;
            Qv[i] = frac0 * bv[i] * u0 * eA0;
        }
        Pp[q] = make_float4(Pv[0], Pv[1], Pv[2], Pv[3]);
        Qp[q] = make_float4(Qv[0], Qv[1], Qv[2], Qv[3]);
    }
}

// ---------------------------------------------------------------------------
// Kernel B: serial scan over the 128 chunks per state.
// ---------------------------------------------------------------------------
__global__ __launch_bounds__(256) void scan_kernel()
{
    int s = blockIdx.x * blockDim.x + threadIdx.x;
    float h = 0.0f;
    for (int kk = 0; kk < Cc; kk += 8) {
        float Pv[8], Qv[8];
#pragma unroll
        for (int j = 0; j < 8; ++j) {
            Pv[j] = g_P[(kk + j) * S_TOT + s];
            Qv[j] = g_Q[(kk + j) * S_TOT + s];
        }
#pragma unroll
        for (int j = 0; j < 8; ++j) {
            g_H0[(kk + j) * S_TOT + s] = h;
            h = fmaf(h, Pv[j], Qv[j]);
        }
    }
}

// ---------------------------------------------------------------------------
// Kernel C: main pass — R4 structure (two-phase, b@j / c@t_idx, 2 streams),
// but with the SLIM dl[16] register table + min-trick:
//   max(dl*A, -10) = A * min(dl, -10/A)   (A<0)
// Phase 2 walks ps (ascending j) and Wr (descending t_idx = 15-j); the Wr
// chain is register-only (4-cyc FADD). ~48 regs freed vs R4's dA[4][16]
// table -> ptxas front-batches more float4 loads (higher MLP) at the SAME
// (256,2) occupancy (128-reg cap: no spill risk, unlike R6's (256,3)).
//   y[t_idx] = sum_n (h0*cumA[t_idx] + PS[j]) * c[t_idx]
// ---------------------------------------------------------------------------
__global__ __launch_bounds__(256, 2) void main_kernel(
    const float* __restrict__ u,
    const float* __restrict__ delta,
    const float* __restrict__ bmat,
    const float* __restrict__ cmat,
    const float* __restrict__ Alog,
    float* __restrict__ y)
{
    int bx = blockIdx.x;
    int dblk = bx & 15;          // 16 d-blocks of 64
    int k    = (bx >> 4) & 127;  // chunk
    int b    = bx >> 11;         // batch

    int tid  = threadIdx.x;
    int ng   = tid & 3;          // n-quad: n = 4*ng .. 4*ng+3
    int dloc = tid >> 2;         // 0..63
    int d    = dblk * 64 + dloc;

    float A[4], invA[4], thr[4];
#pragma unroll
    for (int i = 0; i < 4; ++i) {
        A[i]    = -__expf(Alog[4 * ng + i]);
        invA[i] = 1.0f / (A[i] + 1e-12f);
        thr[i]  = -10.0f / A[i];
    }

    int base_td = (b * Tc + k * Lc) * Dc + d;

    // Phase 1: dl table (16 regs) + W totals
    float dl[Lc];
    float Wr[4] = {0.0f, 0.0f, 0.0f, 0.0f};
#pragma unroll
    for (int t = 0; t < Lc; ++t) {
        dl[t] = delta[base_td + t * Dc];
#pragma unroll
        for (int i = 0; i < 4; ++i)
            Wr[i] += fminf(dl[t], thr[i]);
    }

    float4 h04 = *reinterpret_cast<const float4*>(
        g_H0 + k * S_TOT + (b * Dc + d) * Nc + 4 * ng);
    float h0[4] = {h04.x, h04.y, h04.z, h04.w};

    __shared__ float s_y[Lc * 64];

    float ps[4] = {0.0f, 0.0f, 0.0f, 0.0f};

#pragma unroll
    for (int j = 0; j < Lc; ++j) {
        int t_idx = Lc - 1 - j;
        float uu = u[base_td + j * Dc];
        float4 b4 = *reinterpret_cast<const float4*>(
            bmat + (size_t)(base_td + j * Dc) * Nc + 4 * ng);
        float4 c4 = *reinterpret_cast<const float4*>(
            cmat + (size_t)(base_td + t_idx * Dc) * Nc + 4 * ng);
        float bv[4] = {b4.x, b4.y, b4.z, b4.w};
        float cv[4] = {c4.x, c4.y, c4.z, c4.w};

        float contrib = 0.0f;
#pragma unroll
        for (int i = 0; i < 4; ++i) {
            float cumA = __expf(A[i] * Wr[i]);      // cumprod(eA)[t_idx]
            Wr[i] -= fminf(dl[t_idx], thr[i]);      // register-only chain

            float da = A[i] * fminf(dl[j], thr[i]);
            float eA = __expf(da);
            float frac = (fabsf(da) < 1e-4f) ? (da * invA[i])
                                             : (eA - 1.0f) * invA[i];
            float bu = frac * bv[i] * uu;
            float fw = (j == Lc - 1) ? 1.0f : eA;   // folds at compile time
            ps[i] += bu * fw;                       // ps = PS[j]
            contrib = fmaf(fmaf(h0[i], cumA, ps[i]), cv[i], contrib);
        }
        // reduce over the 4 n-quad lanes (bits 0..1 of lane id)
        contrib += __shfl_xor_sync(0xffffffffu, contrib, 1, 32);
        contrib += __shfl_xor_sync(0xffffffffu, contrib, 2, 32);
        if (ng == 0) s_y[t_idx * 64 + dloc] = contrib;
    }
    __syncthreads();

    // coalesced y writes: 4 rows of 256
#pragma unroll
    for (int r = 0; r < 4; ++r) {
        int idx = tid + r * 256;
        int tt = idx >> 6;
        int dw = idx & 63;
        y[(b * Tc + k * Lc + tt) * Dc + dblk * 64 + dw] = s_y[idx];
    }
}

// ---------------------------------------------------------------------------
extern "C" void kernel_launch(void* const* d_in, const int* in_sizes, int n_in,
                              void* d_out, int out_size)
{
    const float* u     = (const float*)d_in[0];
    const float* delta = (const float*)d_in[1];
    const float* bmat  = (const float*)d_in[2];
    const float* cmat  = (const float*)d_in[3];
    const float* Alog  = (const float*)d_in[4];
    float* y = (float*)d_out;

    pq_kernel<<<Bc * Cc * 4, 256>>>(u, delta, bmat, Alog);
    scan_kernel<<<S_TOT / 256, 256>>>();
    main_kernel<<<Bc * Cc * 16, 256>>>(u, delta, bmat, cmat, Alog, y);
}